// round 5
// baseline (speedup 1.0000x reference)
#include <cuda_runtime.h>
#include <math.h>

#define T_STEPS 512
#define BATCH   64
#define IN_DIM  256
#define HID     512
#define OUT_DIM 256
#define BH      (BATCH * HID)        // 32768
#define M_ROWS  (T_STEPS * BATCH)    // 32768

// Scratch (allocation-free rule: __device__ globals)
__device__ float g_xp[(size_t)M_ROWS * HID];   // xp = x@W_ih^T + b_ih + b_hh
__device__ float g_rnn[(size_t)M_ROWS * HID];  // rnn_out (h history)

// ---- barrier state: monotonic flags + persistent epoch ----
#define SCAN_CTAS 128
#define NGROUPS   4     // batch groups
#define CGS       32    // col groups per batch group
__device__ __align__(128) unsigned g_flags2[NGROUPS][32];  // one 128B line per group
__device__ unsigned g_epoch;

__device__ __forceinline__ unsigned ld_acq(const unsigned* p) {
    unsigned v;
    asm volatile("ld.acquire.gpu.u32 %0, [%1];" : "=r"(v) : "l"(p));
    return v;
}
__device__ __forceinline__ void st_rel(unsigned* p, unsigned v) {
    asm volatile("st.release.gpu.u32 [%0], %1;" :: "l"(p), "r"(v));
}

// fast tanh: rel err ~1e-6, no NaN (clamped)
__device__ __forceinline__ float tanh_fast(float x) {
    float xc = fminf(9.0f, fmaxf(-9.0f, x));
    float e  = exp2f(2.885390081777927f * xc);   // e^(2x)
    return __fdividef(e - 1.0f, e + 1.0f);
}

// -------------------- SGEMM: C[M,N] = A[M,K] @ Bw[N,K]^T + bias --------------------
template<int BM, int BN, int BK, int TM, int TN, int THREADS>
__global__ __launch_bounds__(THREADS)
void sgemm_bt_bias(const float* __restrict__ A,
                   const float* __restrict__ Bw,
                   const float* __restrict__ bias0,
                   const float* __restrict__ bias1,
                   float* __restrict__ C,
                   int M, int N, int K)
{
    __shared__ float As[BK][BM];
    __shared__ float Bs[BK][BN];

    const int tid = threadIdx.x;
    const int tx  = tid % (BN / TN);
    const int ty  = tid / (BN / TN);
    const int m0  = blockIdx.y * BM;
    const int n0  = blockIdx.x * BN;

    float acc[TM][TN];
    #pragma unroll
    for (int i = 0; i < TM; ++i)
        #pragma unroll
        for (int j = 0; j < TN; ++j) acc[i][j] = 0.f;

    for (int k0 = 0; k0 < K; k0 += BK) {
        #pragma unroll
        for (int i = tid; i < (BM * BK) / 4; i += THREADS) {
            int r  = i / (BK / 4);
            int c4 = i % (BK / 4);
            float4 v = *(const float4*)&A[(size_t)(m0 + r) * K + k0 + c4 * 4];
            As[c4 * 4 + 0][r] = v.x;
            As[c4 * 4 + 1][r] = v.y;
            As[c4 * 4 + 2][r] = v.z;
            As[c4 * 4 + 3][r] = v.w;
        }
        #pragma unroll
        for (int i = tid; i < (BN * BK) / 4; i += THREADS) {
            int r  = i / (BK / 4);
            int c4 = i % (BK / 4);
            float4 v = *(const float4*)&Bw[(size_t)(n0 + r) * K + k0 + c4 * 4];
            Bs[c4 * 4 + 0][r] = v.x;
            Bs[c4 * 4 + 1][r] = v.y;
            Bs[c4 * 4 + 2][r] = v.z;
            Bs[c4 * 4 + 3][r] = v.w;
        }
        __syncthreads();

        #pragma unroll
        for (int kk = 0; kk < BK; ++kk) {
            float aR[TM], bR[TN];
            #pragma unroll
            for (int i = 0; i < TM; ++i) aR[i] = As[kk][ty * TM + i];
            #pragma unroll
            for (int j = 0; j < TN; ++j) bR[j] = Bs[kk][tx * TN + j];
            #pragma unroll
            for (int i = 0; i < TM; ++i)
                #pragma unroll
                for (int j = 0; j < TN; ++j)
                    acc[i][j] += aR[i] * bR[j];
        }
        __syncthreads();
    }

    float bj[TN];
    #pragma unroll
    for (int j = 0; j < TN; ++j) {
        int n = n0 + tx * TN + j;
        bj[j] = bias0[n] + (bias1 ? bias1[n] : 0.f);
    }
    #pragma unroll
    for (int i = 0; i < TM; ++i) {
        int m = m0 + ty * TM + i;
        #pragma unroll
        for (int j = 0; j < TN; ++j) {
            int n = n0 + tx * TN + j;
            C[(size_t)m * N + n] = acc[i][j] + bj[j];
        }
    }
}

// -------------------- recurrent scan v4 --------------------
// 128 CTAs = 32 col-groups x 4 batch-groups. CTA: 16 cols x 16 batches.
// Warp shape 8 cols x 4 batches (minimizes unique SMEM traffic).
#define COLS_PER_CTA 16
#define BPC          16
#define WS           516
#define HS           520
#define SMEM_SCAN_BYTES ((COLS_PER_CTA * WS + BPC * HS) * 4)

__global__ __launch_bounds__(256)
void rnn_scan3(const float* __restrict__ Whh,
               float* __restrict__ h_out)
{
    extern __shared__ float sm[];
    float* sW = sm;                        // [16][WS]
    float* sH = sm + COLS_PER_CTA * WS;    // [16][HS]
    __shared__ unsigned s_base;

    const int tid = threadIdx.x;
    const int bid = blockIdx.x;
    const int bh  = bid & 3;
    const int cg  = bid >> 2;

    // warp-shaped mapping: warp covers 8 cols x 4 batches
    const int w = tid >> 5, l = tid & 31;
    const int c  = ((w & 1) << 3) + (l & 7);     // 0..15
    const int bl = ((w >> 1) << 2) + (l >> 3);   // 0..15

    const int colg = cg * COLS_PER_CTA + c;
    const int b    = bh * BPC + bl;
    const int b0   = bh * BPC;

    if (tid == 0) s_base = *(volatile unsigned*)&g_epoch;

    // cache W_hh rows [cg*16, cg*16+16) in SMEM
    for (int i = tid; i < COLS_PER_CTA * (HID / 4); i += 256) {
        int r  = i >> 7;
        int k4 = i & 127;
        float4 v = *(const float4*)&Whh[(size_t)(cg * COLS_PER_CTA + r) * HID + k4 * 4];
        *(float4*)&sW[r * WS + k4 * 4] = v;
    }
    __syncthreads();
    const unsigned base = s_base;

    float my_xp = g_xp[(size_t)b * HID + colg];   // t = 0

    const ulonglong2* h2 = (const ulonglong2*)&sH[bl * HS];
    const ulonglong2* w2 = (const ulonglong2*)&sW[c * WS];

    for (int t = 0; t < T_STEPS; ++t) {
        float acc = my_xp;
        if (t > 0) {
            unsigned long long a01 = 0ull, a23 = 0ull;
            #pragma unroll 8
            for (int k4 = 0; k4 < HID / 4; ++k4) {
                ulonglong2 hv = h2[k4];
                ulonglong2 wv = w2[k4];
                asm("fma.rn.f32x2 %0, %1, %2, %0;" : "+l"(a01) : "l"(hv.x), "l"(wv.x));
                asm("fma.rn.f32x2 %0, %1, %2, %0;" : "+l"(a23) : "l"(hv.y), "l"(wv.y));
            }
            float s0, s1, s2, s3;
            asm("mov.b64 {%0, %1}, %2;" : "=f"(s0), "=f"(s1) : "l"(a01));
            asm("mov.b64 {%0, %1}, %2;" : "=f"(s2), "=f"(s3) : "l"(a23));
            acc += (s0 + s1) + (s2 + s3);
        }
        float hn = tanh_fast(acc);
        g_rnn[(size_t)t * BH + (size_t)b * HID + colg] = hn;

        if (t == T_STEPS - 1) {
            h_out[(size_t)b * HID + colg] = hn;
            break;
        }

        // ---- group barrier (one-hop, monotonic) ----
        const unsigned target = base + (unsigned)t + 1u;
        __syncthreads();
        if (tid == 0)
            st_rel(&g_flags2[bh][cg], target);
        if (tid < 32) {
            bool ok;
            do {
                unsigned v = ld_acq(&g_flags2[bh][tid]);
                ok = __all_sync(0xffffffffu, (int)(v - target) >= 0);
            } while (!ok);
        }
        __syncthreads();

        // ---- stage h[t] rows b0..b0+15 into SMEM; prefetch next xp ----
        const float* src = &g_rnn[(size_t)t * BH + (size_t)b0 * HID];
        #pragma unroll
        for (int i = tid; i < BPC * (HID / 4); i += 256) {
            int r  = i >> 7;
            int k4 = i & 127;
            float4 v = *(const float4*)&src[(size_t)r * HID + k4 * 4];
            *(float4*)&sH[r * HS + k4 * 4] = v;
        }
        my_xp = g_xp[(size_t)(t + 1) * BH + (size_t)b * HID + colg];
        __syncthreads();
    }

    if (bid == 0 && tid == 0)
        *(volatile unsigned*)&g_epoch = base + (unsigned)T_STEPS;
}

// -------------------- launch --------------------
extern "C" void kernel_launch(void* const* d_in, const int* in_sizes, int n_in,
                              void* d_out, int out_size)
{
    const float* x     = (const float*)d_in[0];
    const float* W_ih  = (const float*)d_in[1];
    const float* W_hh  = (const float*)d_in[2];
    const float* b_ih  = (const float*)d_in[3];
    const float* b_hh  = (const float*)d_in[4];
    const float* W_out = (const float*)d_in[5];
    const float* b_out = (const float*)d_in[6];

    float* y = (float*)d_out;
    float* h = y + (size_t)T_STEPS * BATCH * OUT_DIM;

    float* xp  = nullptr;
    float* rnn = nullptr;
    cudaGetSymbolAddress((void**)&xp,  g_xp);
    cudaGetSymbolAddress((void**)&rnn, g_rnn);

    // K1: xp = x @ W_ih^T + b_ih + b_hh
    {
        dim3 grid(HID / 64, M_ROWS / 128);
        sgemm_bt_bias<128, 64, 16, 8, 4, 256><<<grid, 256>>>(
            x, W_ih, b_ih, b_hh, xp, M_ROWS, HID, IN_DIM);
    }

    // K2: recurrence (4 launches/call total -> process launch #6 is this scan,
    // so ncu -s 5 -c 1 profiles it)
    cudaFuncSetAttribute(rnn_scan3, cudaFuncAttributeMaxDynamicSharedMemorySize,
                         SMEM_SCAN_BYTES);
    rnn_scan3<<<SCAN_CTAS, 256, SMEM_SCAN_BYTES>>>(W_hh, h);

    // K3: y = rnn_out @ W_out^T + b_out  — split into two M-halves (same total work)
    {
        dim3 grid(OUT_DIM / 64, (M_ROWS / 2) / 128);
        sgemm_bt_bias<128, 64, 16, 8, 4, 256><<<grid, 256>>>(
            rnn, W_out, b_out, nullptr, y, M_ROWS / 2, OUT_DIM, HID);
        const float* rnn2 = rnn + (size_t)(M_ROWS / 2) * HID;
        float* y2 = y + (size_t)(M_ROWS / 2) * OUT_DIM;
        sgemm_bt_bias<128, 64, 16, 8, 4, 256><<<grid, 256>>>(
            rnn2, W_out, b_out, nullptr, y2, M_ROWS / 2, OUT_DIM, HID);
    }
}